// round 2
// baseline (speedup 1.0000x reference)
#include <cuda_runtime.h>
#include <cuda_bf16.h>

// SNN dense (TTFS) — B=64, IN=1024 (+1 bias row), OUT=1024.
// Plan:
//   K1: stable rank-counting sort of each batch row's spike times (K=1025).
//   K2: per-(b,m) sequential scan over sorted inputs, exact reference math.

#define BATCH 64
#define IN_SZ 1024
#define KTOT 1025          // IN_SZ + bias
#define OUT_SZ 1024
#define MAXT 100000.0f
#define EPSV 1e-10f
#define BIASV 1.0f

// Scratch (device globals; no allocation allowed)
__device__ float g_xs[BATCH][KTOT + 4];   // sorted spike times
__device__ int   g_idx[BATCH][KTOT + 4];  // original indices in firing order

// ---------------------------------------------------------------------------
// Kernel 1: stable counting sort. grid = (9, 64), block = 128.
// Each CTA loads the full row into smem; each thread ranks one element by
// counting (x_j < x_i) || (x_j == x_i && j < i)  — exactly stable ascending,
// matching jnp.argsort.
// ---------------------------------------------------------------------------
__global__ void __launch_bounds__(128) snn_sort_kernel(const float* __restrict__ X) {
    const int b = blockIdx.y;
    __shared__ float sx[KTOT + 3];

    for (int j = threadIdx.x; j < KTOT; j += blockDim.x)
        sx[j] = (j < IN_SZ) ? X[b * IN_SZ + j] : BIASV;
    if (threadIdx.x < 3) sx[KTOT + threadIdx.x] = 3.0e38f;  // pad for float4 reads
    __syncthreads();

    const int i = blockIdx.x * blockDim.x + threadIdx.x;
    if (i >= KTOT) return;

    const float xi = sx[i];
    int r = 0;
    // vectorized scan over shared (broadcast: all lanes read same address)
    const float4* sx4 = reinterpret_cast<const float4*>(sx);
    #pragma unroll 4
    for (int j4 = 0; j4 < (KTOT + 3) / 4; ++j4) {
        float4 v = sx4[j4];
        int j = j4 * 4;
        r += (v.x < xi) || (v.x == xi && (j + 0) < i);
        r += (v.y < xi) || (v.y == xi && (j + 1) < i);
        r += (v.z < xi) || (v.z == xi && (j + 2) < i);
        r += (v.w < xi) || (v.w == xi && (j + 3) < i);
    }
    // padding elements are 3e38 > xi, never counted (xi <= 2.0)
    g_xs[b][r]  = xi;
    g_idx[b][r] = i;
}

// ---------------------------------------------------------------------------
// Kernel 2: the scan. grid = (OUT_SZ / (2*128), BATCH) = (4, 64), block = 128.
// Each thread handles 2 adjacent output neurons (float2 weight loads).
// Exact reference arithmetic: _rn add/mul (no FMA contraction, same
// association as cumsum), exact clip order, precise division, identical mask
// chain.
// ---------------------------------------------------------------------------
__global__ void __launch_bounds__(128) snn_scan_kernel(const float* __restrict__ W,
                                                       float* __restrict__ out) {
    const int b = blockIdx.y;
    __shared__ float sx[KTOT + 1];
    __shared__ int   sidx[KTOT];

    for (int j = threadIdx.x; j < KTOT; j += blockDim.x) {
        sx[j]   = g_xs[b][j];
        sidx[j] = g_idx[b][j];
    }
    if (threadIdx.x == 0) sx[KTOT] = MAXT;  // next_x sentinel for last k
    __syncthreads();

    const int m = blockIdx.x * (2 * blockDim.x) + 2 * threadIdx.x;
    const float* Wm = W + m;

    float cw0 = 0.f, cwt0 = 0.f, best0 = MAXT;
    float cw1 = 0.f, cwt1 = 0.f, best1 = MAXT;

    float x = sx[0];
    #pragma unroll 4
    for (int k = 0; k < KTOT; ++k) {
        const int r = sidx[k];
        const float2 w = *reinterpret_cast<const float2*>(Wm + r * OUT_SZ);
        const float nx = sx[k + 1];

        // ---- neuron m ----
        cw0  = __fadd_rn(cw0, w.x);
        cwt0 = __fadd_rn(cwt0, __fmul_rn(w.x, x));
        {
            float den = fminf(fmaxf(__fadd_rn(cw0, -1.0f), EPSV), MAXT);
            float cand = __fdiv_rn(cwt0, den);
            float o = (cw0 < 1.0f) ? MAXT : cand;
            o = (cand < x) ? MAXT : o;
            o = (o > nx) ? MAXT : o;
            best0 = fminf(best0, o);
        }
        // ---- neuron m+1 ----
        cw1  = __fadd_rn(cw1, w.y);
        cwt1 = __fadd_rn(cwt1, __fmul_rn(w.y, x));
        {
            float den = fminf(fmaxf(__fadd_rn(cw1, -1.0f), EPSV), MAXT);
            float cand = __fdiv_rn(cwt1, den);
            float o = (cw1 < 1.0f) ? MAXT : cand;
            o = (cand < x) ? MAXT : o;
            o = (o > nx) ? MAXT : o;
            best1 = fminf(best1, o);
        }
        x = nx;
    }

    out[b * OUT_SZ + m]     = best0;
    out[b * OUT_SZ + m + 1] = best1;
}

// ---------------------------------------------------------------------------
extern "C" void kernel_launch(void* const* d_in, const int* in_sizes, int n_in,
                              void* d_out, int out_size) {
    const float* X = (const float*)d_in[0];
    const float* W = (const float*)d_in[1];
    // Defensive: X is BATCH*IN_SZ elements, W is (IN_SZ+1)*OUT_SZ.
    if (n_in >= 2 && in_sizes[0] != BATCH * IN_SZ && in_sizes[1] == BATCH * IN_SZ) {
        X = (const float*)d_in[1];
        W = (const float*)d_in[0];
    }
    float* out = (float*)d_out;

    dim3 gs((KTOT + 127) / 128, BATCH);       // (9, 64)
    snn_sort_kernel<<<gs, 128>>>(X);

    dim3 gm(OUT_SZ / 256, BATCH);             // (4, 64)
    snn_scan_kernel<<<gm, 128>>>(W, out);
}

// round 3
// speedup vs baseline: 3.0407x; 3.0407x over previous
#include <cuda_runtime.h>
#include <cuda_bf16.h>

// SNN dense (TTFS) — B=64, IN=1024 (+1 bias row), OUT=1024.
//   K1: stable rank-counting sort of each batch row's spike times (K=1025).
//   K2: chunk-parallel scan: 16 warps split the sorted k-axis; pass1 chunk
//       sums -> exclusive prefix in shared -> pass2 scan with offsets.

#define BATCH 64
#define IN_SZ 1024
#define KTOT 1025          // IN_SZ + bias
#define OUT_SZ 1024
#define MAXT 100000.0f
#define EPSV 1e-10f
#define BIASV 1.0f

#define NW 16              // warps (K-chunks) per CTA
#define CHUNK ((KTOT + NW - 1) / NW)   // 65
#define MBLK 64            // outputs per CTA (2 per lane)

// Scratch (device globals; no allocation allowed)
__device__ float g_xs[BATCH][KTOT + 4];   // sorted spike times
__device__ int   g_idx[BATCH][KTOT + 4];  // original indices in firing order

// ---------------------------------------------------------------------------
// Kernel 1: stable counting sort. grid = (9, 64), block = 128.
// ---------------------------------------------------------------------------
__global__ void __launch_bounds__(128) snn_sort_kernel(const float* __restrict__ X) {
    const int b = blockIdx.y;
    __shared__ float sx[KTOT + 3];

    for (int j = threadIdx.x; j < KTOT; j += blockDim.x)
        sx[j] = (j < IN_SZ) ? X[b * IN_SZ + j] : BIASV;
    if (threadIdx.x < 3) sx[KTOT + threadIdx.x] = 3.0e38f;  // pad for float4 reads
    __syncthreads();

    const int i = blockIdx.x * blockDim.x + threadIdx.x;
    if (i >= KTOT) return;

    const float xi = sx[i];
    int r = 0;
    const float4* sx4 = reinterpret_cast<const float4*>(sx);
    #pragma unroll 4
    for (int j4 = 0; j4 < (KTOT + 3) / 4; ++j4) {
        float4 v = sx4[j4];
        int j = j4 * 4;
        r += (v.x < xi) || (v.x == xi && (j + 0) < i);
        r += (v.y < xi) || (v.y == xi && (j + 1) < i);
        r += (v.z < xi) || (v.z == xi && (j + 2) < i);
        r += (v.w < xi) || (v.w == xi && (j + 3) < i);
    }
    g_xs[b][r]  = xi;
    g_idx[b][r] = i;
}

// ---------------------------------------------------------------------------
// Kernel 2: chunk-parallel scan. grid = (OUT_SZ/MBLK, BATCH) = (16, 64),
// block = 512 (16 warps). Warp w owns k in [w*CHUNK, min((w+1)*CHUNK, KTOT));
// lane L owns outputs m = mbase + 2L, 2L+1.
// ---------------------------------------------------------------------------
__global__ void __launch_bounds__(512) snn_scan_kernel(const float* __restrict__ W,
                                                       float* __restrict__ out) {
    const int b = blockIdx.y;
    const int mbase = blockIdx.x * MBLK;

    __shared__ float sx[KTOT + 1];
    __shared__ int   sidx[KTOT];
    __shared__ float pw[NW][MBLK];   // pass1 chunk sums of w
    __shared__ float pt[NW][MBLK];   // pass1 chunk sums of w*x
    __shared__ float pmin[NW][MBLK]; // per-chunk candidate minima

    for (int j = threadIdx.x; j < KTOT; j += blockDim.x) {
        sx[j]   = g_xs[b][j];
        sidx[j] = g_idx[b][j];
    }
    if (threadIdx.x == 0) sx[KTOT] = MAXT;  // next_x sentinel
    __syncthreads();

    const int w    = threadIdx.x >> 5;
    const int lane = threadIdx.x & 31;
    const float* Wm = W + mbase + 2 * lane;

    const int k0 = w * CHUNK;
    const int k1 = (k0 + CHUNK < KTOT) ? (k0 + CHUNK) : KTOT;

    // ---- pass 1: chunk partial sums ----
    float s0 = 0.f, t0 = 0.f, s1 = 0.f, t1 = 0.f;
    #pragma unroll 4
    for (int k = k0; k < k1; ++k) {
        const float x = sx[k];
        const float2 wt = *reinterpret_cast<const float2*>(Wm + sidx[k] * OUT_SZ);
        s0 += wt.x; t0 += wt.x * x;
        s1 += wt.y; t1 += wt.y * x;
    }
    pw[w][2 * lane]     = s0;  pt[w][2 * lane]     = t0;
    pw[w][2 * lane + 1] = s1;  pt[w][2 * lane + 1] = t1;
    __syncthreads();

    // ---- exclusive prefix over earlier chunks ----
    float cw0 = 0.f, ct0 = 0.f, cw1 = 0.f, ct1 = 0.f;
    for (int c = 0; c < w; ++c) {
        cw0 += pw[c][2 * lane];     ct0 += pt[c][2 * lane];
        cw1 += pw[c][2 * lane + 1]; ct1 += pt[c][2 * lane + 1];
    }

    // ---- pass 2: scan chunk, evaluate candidates ----
    float best0 = MAXT, best1 = MAXT;
    #pragma unroll 4
    for (int k = k0; k < k1; ++k) {
        const float x  = sx[k];
        const float nx = sx[k + 1];
        const float2 wt = *reinterpret_cast<const float2*>(Wm + sidx[k] * OUT_SZ);

        cw0 += wt.x; ct0 += wt.x * x;
        {
            float den  = fminf(fmaxf(cw0 - 1.0f, EPSV), MAXT);
            float cand = __fdividef(ct0, den);
            bool bad = (cw0 < 1.0f) | (cand < x) | (cand > nx);
            best0 = fminf(best0, bad ? MAXT : cand);
        }
        cw1 += wt.y; ct1 += wt.y * x;
        {
            float den  = fminf(fmaxf(cw1 - 1.0f, EPSV), MAXT);
            float cand = __fdividef(ct1, den);
            bool bad = (cw1 < 1.0f) | (cand < x) | (cand > nx);
            best1 = fminf(best1, bad ? MAXT : cand);
        }
    }
    pmin[w][2 * lane]     = best0;
    pmin[w][2 * lane + 1] = best1;
    __syncthreads();

    // ---- final min across chunks (warp 0) ----
    if (w == 0) {
        float b0 = MAXT, b1 = MAXT;
        #pragma unroll
        for (int c = 0; c < NW; ++c) {
            b0 = fminf(b0, pmin[c][2 * lane]);
            b1 = fminf(b1, pmin[c][2 * lane + 1]);
        }
        out[b * OUT_SZ + mbase + 2 * lane]     = b0;
        out[b * OUT_SZ + mbase + 2 * lane + 1] = b1;
    }
}

// ---------------------------------------------------------------------------
extern "C" void kernel_launch(void* const* d_in, const int* in_sizes, int n_in,
                              void* d_out, int out_size) {
    const float* X = (const float*)d_in[0];
    const float* W = (const float*)d_in[1];
    if (n_in >= 2 && in_sizes[0] != BATCH * IN_SZ && in_sizes[1] == BATCH * IN_SZ) {
        X = (const float*)d_in[1];
        W = (const float*)d_in[0];
    }
    float* out = (float*)d_out;

    dim3 gs((KTOT + 127) / 128, BATCH);       // (9, 64)
    snn_sort_kernel<<<gs, 128>>>(X);

    dim3 gm(OUT_SZ / MBLK, BATCH);            // (16, 64)
    snn_scan_kernel<<<gm, 512>>>(W, out);
}